// round 14
// baseline (speedup 1.0000x reference)
#include <cuda_runtime.h>
#include <math.h>
#include <stdint.h>

#define NN   50000
#define EE   800000
#define HH   8
#define H1C  128
#define OC   40
#define SLOPE 0.2f
#define NEG_INF __int_as_float(0xff800000)

#define SCAN_B 1024
#define NBLK   ((NN + SCAN_B - 1) / SCAN_B)   // 49
#define AGG_BLOCKS 1184                        // 8 per SM x 148

// ---------------- scratch -----------------------------------------------------
__device__ float g_h1[NN * H1C];
__device__ float g_as1[NN * HH];
__device__ float g_ad1[NN * HH];
__device__ float g_agg1[NN * H1C];
__device__ float g_h2[NN * OC];
__device__ float g_as2[NN];
__device__ float g_ad2[NN];
__device__ int   g_deg[NN];
__device__ int   g_off[NN];
__device__ int   g_cur[NN];
__device__ int   g_bsum[NBLK];
__device__ int   g_list[EE];           // src ids grouped by dst
__device__ int   g_is64;
__device__ int   g_work1;
__device__ int   g_work2;

// ---------------- helpers -----------------------------------------------------
__device__ __forceinline__ float leaky(float v) {
    return (v >= 0.0f) ? v : SLOPE * v;
}
__device__ __forceinline__ uint32_t f2tf(float f) {
    uint32_t u;
    asm("cvt.rna.tf32.f32 %0, %1;" : "=r"(u) : "f"(f));
    return u;
}
__device__ __forceinline__ void mma_tf32(float* d, const uint32_t* a, const uint32_t* b) {
    asm volatile(
        "mma.sync.aligned.m16n8k8.row.col.f32.tf32.tf32.f32 "
        "{%0,%1,%2,%3}, {%4,%5,%6,%7}, {%8,%9}, {%0,%1,%2,%3};\n"
        : "+f"(d[0]), "+f"(d[1]), "+f"(d[2]), "+f"(d[3])
        : "r"(a[0]), "r"(a[1]), "r"(a[2]), "r"(a[3]), "r"(b[0]), "r"(b[1]));
}

// ---------------- CSR build ----------------------------------------------------
__global__ void k_detect(const unsigned int* p) {
    int t = threadIdx.x;                   // 32
    unsigned int v = p[2 * t + 1];
    int any = __any_sync(0xffffffff, v != 0);
    if (t == 0) g_is64 = any ? 0 : 1;
}

__global__ void k_zero() {
    int i = blockIdx.x * blockDim.x + threadIdx.x;
    if (i < NN) g_deg[i] = 0;
}

__global__ void k_count(const void* __restrict__ ei) {
    int base = (blockIdx.x * blockDim.x + threadIdx.x) * 4;
    if (base >= EE) return;
    int d0, d1, d2, d3;
    if (g_is64) {
        const longlong2* p = (const longlong2*)((const long long*)ei + EE + base);
        longlong2 a = p[0];
        longlong2 b = p[1];
        d0 = (int)a.x; d1 = (int)a.y; d2 = (int)b.x; d3 = (int)b.y;
    } else {
        int4 a = *(const int4*)((const int*)ei + EE + base);
        d0 = a.x; d1 = a.y; d2 = a.z; d3 = a.w;
    }
    atomicAdd(&g_deg[d0], 1);
    atomicAdd(&g_deg[d1], 1);
    atomicAdd(&g_deg[d2], 1);
    atomicAdd(&g_deg[d3], 1);
}

__global__ void k_scan1() {
    __shared__ int warpsum[32];
    int tid = threadIdx.x;
    int i = blockIdx.x * SCAN_B + tid;
    int v = (i < NN) ? g_deg[i] : 0;
    int x = v;
#pragma unroll
    for (int o = 1; o < 32; o <<= 1) {
        int y = __shfl_up_sync(0xffffffff, x, o);
        if ((tid & 31) >= o) x += y;
    }
    if ((tid & 31) == 31) warpsum[tid >> 5] = x;
    __syncthreads();
    if (tid < 32) {
        int w = warpsum[tid];
#pragma unroll
        for (int o = 1; o < 32; o <<= 1) {
            int y = __shfl_up_sync(0xffffffff, w, o);
            if (tid >= o) w += y;
        }
        warpsum[tid] = w;
    }
    __syncthreads();
    int blockpart = (tid >= 32) ? warpsum[(tid >> 5) - 1] : 0;
    if (i < NN) g_off[i] = blockpart + x - v;
    if (tid == SCAN_B - 1) g_bsum[blockIdx.x] = blockpart + x;
}

// scan of block sums fused in (every block computes the 49-entry prefix), plus
// work-counter reset for the dynamic agg kernels.
__global__ void k_scan3() {
    __shared__ int sboff[64];
    __shared__ int w0s;
    int tid = threadIdx.x;                 // 256
    if (tid < 64) {
        int v = (tid < NBLK) ? g_bsum[tid] : 0;
        int x = v;
#pragma unroll
        for (int o = 1; o < 32; o <<= 1) {
            int y = __shfl_up_sync(0xffffffff, x, o);
            if ((tid & 31) >= o) x += y;
        }
        if (tid == 31) w0s = x;
        sboff[tid] = x - v;
    }
    __syncthreads();
    if (tid >= 32 && tid < 64) sboff[tid] += w0s;
    __syncthreads();
    int i = blockIdx.x * blockDim.x + tid;
    if (i < NN) {
        int o = g_off[i] + sboff[i / SCAN_B];
        g_off[i] = o;
        g_cur[i] = o;
    }
    if (blockIdx.x == 0 && tid == 0) { g_work1 = 0; g_work2 = 0; }
}

__global__ void k_fill(const void* __restrict__ ei) {
    int base = (blockIdx.x * blockDim.x + threadIdx.x) * 4;
    if (base >= EE) return;
    int s0, s1, s2v, s3, d0, d1, d2, d3;
    if (g_is64) {
        const longlong2* ps = (const longlong2*)((const long long*)ei + base);
        const longlong2* pd = (const longlong2*)((const long long*)ei + EE + base);
        longlong2 sa = ps[0], sb = ps[1];
        longlong2 da = pd[0], db = pd[1];
        s0 = (int)sa.x; s1 = (int)sa.y; s2v = (int)sb.x; s3 = (int)sb.y;
        d0 = (int)da.x; d1 = (int)da.y; d2 = (int)db.x; d3 = (int)db.y;
    } else {
        int4 sa = *(const int4*)((const int*)ei + base);
        int4 da = *(const int4*)((const int*)ei + EE + base);
        s0 = sa.x; s1 = sa.y; s2v = sa.z; s3 = sa.w;
        d0 = da.x; d1 = da.y; d2 = da.z; d3 = da.w;
    }
    g_list[atomicAdd(&g_cur[d0], 1)] = s0;
    g_list[atomicAdd(&g_cur[d1], 1)] = s1;
    g_list[atomicAdd(&g_cur[d2], 1)] = s2v;
    g_list[atomicAdd(&g_cur[d3], 1)] = s3;
}

// ---------------- GEMM1: tf32 tensor-core, fused attention halves --------------
__global__ void k_gemm1(const float* __restrict__ X, const float* __restrict__ W,
                        const float* __restrict__ aS, const float* __restrict__ aD) {
    __shared__ float As[128][36];
    __shared__ float Bs[32][136];
    const int tid  = threadIdx.x;    // 256
    const int wid  = tid >> 5, lane = tid & 31;
    const int g    = lane >> 2, tg = lane & 3;
    const int wm   = wid >> 2, wn = wid & 3;
    const int m0   = wm * 64, n0 = wn * 32;
    const int row0 = blockIdx.x * 128;

    float d[4][4][4];
#pragma unroll
    for (int mi = 0; mi < 4; mi++)
#pragma unroll
        for (int nj = 0; nj < 4; nj++)
#pragma unroll
            for (int r = 0; r < 4; r++) d[mi][nj][r] = 0.0f;

    for (int kc = 0; kc < 128; kc += 32) {
#pragma unroll
        for (int it = 0; it < 4; it++) {
            int f = tid + it * 256;
            int r = f >> 3, q = f & 7;
            int gr = row0 + r;
            float4 v = make_float4(0.f, 0.f, 0.f, 0.f);
            if (gr < NN) v = *(const float4*)&X[gr * 128 + kc + q * 4];
            uint4 t = make_uint4(f2tf(v.x), f2tf(v.y), f2tf(v.z), f2tf(v.w));
            *(uint4*)&As[r][q * 4] = t;
        }
#pragma unroll
        for (int it = 0; it < 4; it++) {
            int f = tid + it * 256;
            int r = f >> 5, q = f & 31;
            float4 v = *(const float4*)&W[(kc + r) * 128 + q * 4];
            uint4 t = make_uint4(f2tf(v.x), f2tf(v.y), f2tf(v.z), f2tf(v.w));
            *(uint4*)&Bs[r][q * 4] = t;
        }
        __syncthreads();
#pragma unroll
        for (int ks = 0; ks < 4; ks++) {
            uint32_t a[4][4];
#pragma unroll
            for (int mi = 0; mi < 4; mi++) {
                int ra = m0 + mi * 16 + g;
                a[mi][0] = __float_as_uint(As[ra][ks * 8 + tg]);
                a[mi][1] = __float_as_uint(As[ra + 8][ks * 8 + tg]);
                a[mi][2] = __float_as_uint(As[ra][ks * 8 + tg + 4]);
                a[mi][3] = __float_as_uint(As[ra + 8][ks * 8 + tg + 4]);
            }
            uint32_t b[4][2];
#pragma unroll
            for (int nj = 0; nj < 4; nj++) {
                int cb = n0 + nj * 8 + g;
                b[nj][0] = __float_as_uint(Bs[ks * 8 + tg][cb]);
                b[nj][1] = __float_as_uint(Bs[ks * 8 + tg + 4][cb]);
            }
#pragma unroll
            for (int mi = 0; mi < 4; mi++)
#pragma unroll
                for (int nj = 0; nj < 4; nj++)
                    mma_tf32(d[mi][nj], a[mi], b[nj]);
        }
        __syncthreads();
    }

    float a_s0[4], a_s1[4], a_d0[4], a_d1[4];
#pragma unroll
    for (int nj = 0; nj < 4; nj++) {
        int c = n0 + nj * 8 + tg * 2;
        a_s0[nj] = aS[c]; a_s1[nj] = aS[c + 1];
        a_d0[nj] = aD[c]; a_d1[nj] = aD[c + 1];
    }
    const int h0 = n0 >> 4;

#pragma unroll
    for (int mi = 0; mi < 4; mi++) {
        int rowA = row0 + m0 + mi * 16 + g;
        int rowB = rowA + 8;
        bool okA = rowA < NN, okB = rowB < NN;
#pragma unroll
        for (int nj = 0; nj < 4; nj++) {
            int col = n0 + nj * 8 + tg * 2;
            if (okA) *(float2*)&g_h1[rowA * 128 + col] = make_float2(d[mi][nj][0], d[mi][nj][1]);
            if (okB) *(float2*)&g_h1[rowB * 128 + col] = make_float2(d[mi][nj][2], d[mi][nj][3]);
        }
        float pA0 = 0, pA1 = 0, pB0 = 0, pB1 = 0;
        float qA0 = 0, qA1 = 0, qB0 = 0, qB1 = 0;
#pragma unroll
        for (int nj = 0; nj < 2; nj++) {
            pA0 += d[mi][nj][0] * a_s0[nj] + d[mi][nj][1] * a_s1[nj];
            pB0 += d[mi][nj][2] * a_s0[nj] + d[mi][nj][3] * a_s1[nj];
            qA0 += d[mi][nj][0] * a_d0[nj] + d[mi][nj][1] * a_d1[nj];
            qB0 += d[mi][nj][2] * a_d0[nj] + d[mi][nj][3] * a_d1[nj];
        }
#pragma unroll
        for (int nj = 2; nj < 4; nj++) {
            pA1 += d[mi][nj][0] * a_s0[nj] + d[mi][nj][1] * a_s1[nj];
            pB1 += d[mi][nj][2] * a_s0[nj] + d[mi][nj][3] * a_s1[nj];
            qA1 += d[mi][nj][0] * a_d0[nj] + d[mi][nj][1] * a_d1[nj];
            qB1 += d[mi][nj][2] * a_d0[nj] + d[mi][nj][3] * a_d1[nj];
        }
#pragma unroll
        for (int o = 1; o <= 2; o <<= 1) {
            pA0 += __shfl_xor_sync(0xffffffff, pA0, o);
            pA1 += __shfl_xor_sync(0xffffffff, pA1, o);
            pB0 += __shfl_xor_sync(0xffffffff, pB0, o);
            pB1 += __shfl_xor_sync(0xffffffff, pB1, o);
            qA0 += __shfl_xor_sync(0xffffffff, qA0, o);
            qA1 += __shfl_xor_sync(0xffffffff, qA1, o);
            qB0 += __shfl_xor_sync(0xffffffff, qB0, o);
            qB1 += __shfl_xor_sync(0xffffffff, qB1, o);
        }
        if (tg == 0) {
            if (okA) {
                g_as1[rowA * 8 + h0] = pA0; g_as1[rowA * 8 + h0 + 1] = pA1;
                g_ad1[rowA * 8 + h0] = qA0; g_ad1[rowA * 8 + h0 + 1] = qA1;
            }
            if (okB) {
                g_as1[rowB * 8 + h0] = pB0; g_as1[rowB * 8 + h0 + 1] = pB1;
                g_ad1[rowB * 8 + h0] = qB0; g_ad1[rowB * 8 + h0 + 1] = qB1;
            }
        }
    }
}

// ---------------- layer1 aggregation: dynamic warp/node, 4-deep pipeline -------
__global__ void k_node_agg1(const float* __restrict__ b1) {
    int lane = threadIdx.x & 31;
    int my_h = lane >> 2;

    while (true) {
        int n;
        if (lane == 0) n = atomicAdd(&g_work1, 1);
        n = __shfl_sync(0xffffffff, n, 0);
        if (n >= NN) break;

        float ad = 0.0f, as_self = 0.0f;
        if (lane < 8) {
            ad      = g_ad1[n * 8 + lane];
            as_self = g_as1[n * 8 + lane];
        }
        float ex = (lane < 8) ? __expf(leaky(as_self + ad)) : 0.0f;
        float den = ex;
        float exb = __shfl_sync(0xffffffff, ex, my_h);
        float4 hv = *(const float4*)&g_h1[n * 128 + lane * 4];
        float4 acc = make_float4(exb * hv.x, exb * hv.y, exb * hv.z, exb * hv.w);

        int beg = g_off[n];
        int end = beg + g_deg[n];
        int i = beg;
        for (; i + 3 < end; i += 4) {
            int s0 = g_list[i], s1 = g_list[i + 1], s2 = g_list[i + 2], s3 = g_list[i + 3];
            float r0 = 0.f, r1 = 0.f, r2 = 0.f, r3 = 0.f;
            if (lane < 8) {
                r0 = g_as1[s0 * 8 + lane];
                r1 = g_as1[s1 * 8 + lane];
                r2 = g_as1[s2 * 8 + lane];
                r3 = g_as1[s3 * 8 + lane];
            }
            float4 h0 = *(const float4*)&g_h1[s0 * 128 + lane * 4];
            float4 h1 = *(const float4*)&g_h1[s1 * 128 + lane * 4];
            float4 h2 = *(const float4*)&g_h1[s2 * 128 + lane * 4];
            float4 h3 = *(const float4*)&g_h1[s3 * 128 + lane * 4];
            float e0 = (lane < 8) ? __expf(leaky(r0 + ad)) : 0.0f;
            float e1 = (lane < 8) ? __expf(leaky(r1 + ad)) : 0.0f;
            float e2 = (lane < 8) ? __expf(leaky(r2 + ad)) : 0.0f;
            float e3 = (lane < 8) ? __expf(leaky(r3 + ad)) : 0.0f;
            den += (e0 + e1) + (e2 + e3);
            float eb0 = __shfl_sync(0xffffffff, e0, my_h);
            float eb1 = __shfl_sync(0xffffffff, e1, my_h);
            float eb2 = __shfl_sync(0xffffffff, e2, my_h);
            float eb3 = __shfl_sync(0xffffffff, e3, my_h);
            acc.x += eb0 * h0.x + eb1 * h1.x + eb2 * h2.x + eb3 * h3.x;
            acc.y += eb0 * h0.y + eb1 * h1.y + eb2 * h2.y + eb3 * h3.y;
            acc.z += eb0 * h0.z + eb1 * h1.z + eb2 * h2.z + eb3 * h3.z;
            acc.w += eb0 * h0.w + eb1 * h1.w + eb2 * h2.w + eb3 * h3.w;
        }
        for (; i < end; i++) {
            int s = g_list[i];
            float e = 0.0f;
            if (lane < 8) e = __expf(leaky(g_as1[s * 8 + lane] + ad));
            den += e;
            float eb = __shfl_sync(0xffffffff, e, my_h);
            float4 h = *(const float4*)&g_h1[s * 128 + lane * 4];
            acc.x += eb * h.x; acc.y += eb * h.y;
            acc.z += eb * h.z; acc.w += eb * h.w;
        }
        float denb = __shfl_sync(0xffffffff, den, my_h);
        float inv = 1.0f / denb;
        float4 bv = *(const float4*)&b1[lane * 4];
        float4 o;
        o.x = fmaxf(acc.x * inv + bv.x, 0.0f);
        o.y = fmaxf(acc.y * inv + bv.y, 0.0f);
        o.z = fmaxf(acc.z * inv + bv.z, 0.0f);
        o.w = fmaxf(acc.w * inv + bv.w, 0.0f);
        *(float4*)&g_agg1[n * 128 + lane * 4] = o;
    }
}

// ---------------- GEMM2: tf32 tensor-core, 256 rows x 40 cols per block --------
__global__ void k_gemm2(const float* __restrict__ W,
                        const float* __restrict__ aS, const float* __restrict__ aD) {
    __shared__ float As[256][36];
    __shared__ float Bs[32][40];
    const int tid  = threadIdx.x;   // 256
    const int wid  = tid >> 5, lane = tid & 31;
    const int g    = lane >> 2, tg = lane & 3;
    const int m0   = wid * 32;
    const int row0 = blockIdx.x * 256;

    float d[2][5][4];
#pragma unroll
    for (int mi = 0; mi < 2; mi++)
#pragma unroll
        for (int f = 0; f < 5; f++)
#pragma unroll
            for (int r = 0; r < 4; r++) d[mi][f][r] = 0.0f;

    for (int kc = 0; kc < 128; kc += 32) {
#pragma unroll
        for (int it = 0; it < 8; it++) {
            int f = tid + it * 256;
            int r = f >> 3, q = f & 7;
            int gr = row0 + r;
            float4 v = make_float4(0.f, 0.f, 0.f, 0.f);
            if (gr < NN) v = *(const float4*)&g_agg1[gr * 128 + kc + q * 4];
            uint4 t = make_uint4(f2tf(v.x), f2tf(v.y), f2tf(v.z), f2tf(v.w));
            *(uint4*)&As[r][q * 4] = t;
        }
        for (int f = tid; f < 320; f += 256) {
            int r = f / 10, q = f % 10;
            float4 v = *(const float4*)&W[(kc + r) * 40 + q * 4];
            uint4 t = make_uint4(f2tf(v.x), f2tf(v.y), f2tf(v.z), f2tf(v.w));
            *(uint4*)&Bs[r][q * 4] = t;
        }
        __syncthreads();
#pragma unroll
        for (int ks = 0; ks < 4; ks++) {
            uint32_t a[2][4];
#pragma unroll
            for (int mi = 0; mi < 2; mi++) {
                int ra = m0 + mi * 16 + g;
                a[mi][0] = __float_as_uint(As[ra][ks * 8 + tg]);
                a[mi][1] = __float_as_uint(As[ra + 8][ks * 8 + tg]);
                a[mi][2] = __float_as_uint(As[ra][ks * 8 + tg + 4]);
                a[mi][3] = __float_as_uint(As[ra + 8][ks * 8 + tg + 4]);
            }
            uint32_t b[5][2];
#pragma unroll
            for (int f = 0; f < 5; f++) {
                int cb = f * 8 + g;
                b[f][0] = __float_as_uint(Bs[ks * 8 + tg][cb]);
                b[f][1] = __float_as_uint(Bs[ks * 8 + tg + 4][cb]);
            }
#pragma unroll
            for (int mi = 0; mi < 2; mi++)
#pragma unroll
                for (int f = 0; f < 5; f++)
                    mma_tf32(d[mi][f], a[mi], b[f]);
        }
        __syncthreads();
    }

    float a_s0[5], a_s1[5], a_d0[5], a_d1[5];
#pragma unroll
    for (int f = 0; f < 5; f++) {
        int c = f * 8 + tg * 2;
        a_s0[f] = aS[c]; a_s1[f] = aS[c + 1];
        a_d0[f] = aD[c]; a_d1[f] = aD[c + 1];
    }

#pragma unroll
    for (int mi = 0; mi < 2; mi++) {
        int rowA = row0 + m0 + mi * 16 + g;
        int rowB = rowA + 8;
        bool okA = rowA < NN, okB = rowB < NN;
#pragma unroll
        for (int f = 0; f < 5; f++) {
            int col = f * 8 + tg * 2;
            if (okA) *(float2*)&g_h2[rowA * OC + col] = make_float2(d[mi][f][0], d[mi][f][1]);
            if (okB) *(float2*)&g_h2[rowB * OC + col] = make_float2(d[mi][f][2], d[mi][f][3]);
        }
        float pA = 0, pB = 0, qA = 0, qB = 0;
#pragma unroll
        for (int f = 0; f < 5; f++) {
            pA += d[mi][f][0] * a_s0[f] + d[mi][f][1] * a_s1[f];
            pB += d[mi][f][2] * a_s0[f] + d[mi][f][3] * a_s1[f];
            qA += d[mi][f][0] * a_d0[f] + d[mi][f][1] * a_d1[f];
            qB += d[mi][f][2] * a_d0[f] + d[mi][f][3] * a_d1[f];
        }
#pragma unroll
        for (int o = 1; o <= 2; o <<= 1) {
            pA += __shfl_xor_sync(0xffffffff, pA, o);
            pB += __shfl_xor_sync(0xffffffff, pB, o);
            qA += __shfl_xor_sync(0xffffffff, qA, o);
            qB += __shfl_xor_sync(0xffffffff, qB, o);
        }
        if (tg == 0) {
            if (okA) { g_as2[rowA] = pA; g_ad2[rowA] = qA; }
            if (okB) { g_as2[rowB] = pB; g_ad2[rowB] = qB; }
        }
    }
}

// ---------------- layer2 aggregation + log_softmax: dynamic warp/node ----------
__global__ void k_node_agg2(const float* __restrict__ b2, float* __restrict__ out) {
    int lane = threadIdx.x & 31;

    while (true) {
        int n;
        if (lane == 0) n = atomicAdd(&g_work2, 1);
        n = __shfl_sync(0xffffffff, n, 0);
        if (n >= NN) break;

        float ad = g_ad2[n];
        float ex = __expf(leaky(g_as2[n] + ad));
        float den = ex;
        float4 acc = make_float4(0.f, 0.f, 0.f, 0.f);
        if (lane < 10) {
            float4 h = *(const float4*)&g_h2[n * OC + lane * 4];
            acc.x = ex * h.x; acc.y = ex * h.y; acc.z = ex * h.z; acc.w = ex * h.w;
        }

        int beg = g_off[n];
        int end = beg + g_deg[n];
        int i = beg;
        for (; i + 1 < end; i += 2) {
            int s0 = g_list[i];
            int s1 = g_list[i + 1];
            float r0 = g_as2[s0];
            float r1 = g_as2[s1];
            float4 h0 = make_float4(0.f, 0.f, 0.f, 0.f);
            float4 h1 = make_float4(0.f, 0.f, 0.f, 0.f);
            if (lane < 10) {
                h0 = *(const float4*)&g_h2[s0 * OC + lane * 4];
                h1 = *(const float4*)&g_h2[s1 * OC + lane * 4];
            }
            float e0 = __expf(leaky(r0 + ad));
            float e1 = __expf(leaky(r1 + ad));
            den += e0 + e1;
            acc.x += e0 * h0.x + e1 * h1.x;
            acc.y += e0 * h0.y + e1 * h1.y;
            acc.z += e0 * h0.z + e1 * h1.z;
            acc.w += e0 * h0.w + e1 * h1.w;
        }
        if (i < end) {
            int s = g_list[i];
            float e = __expf(leaky(g_as2[s] + ad));
            den += e;
            if (lane < 10) {
                float4 h = *(const float4*)&g_h2[s * OC + lane * 4];
                acc.x += e * h.x; acc.y += e * h.y;
                acc.z += e * h.z; acc.w += e * h.w;
            }
        }

        float inv = 1.0f / den;
        float4 v = make_float4(NEG_INF, NEG_INF, NEG_INF, NEG_INF);
        if (lane < 10) {
            v.x = acc.x * inv + b2[lane * 4];
            v.y = acc.y * inv + b2[lane * 4 + 1];
            v.z = acc.z * inv + b2[lane * 4 + 2];
            v.w = acc.w * inv + b2[lane * 4 + 3];
        }
        float m = fmaxf(fmaxf(v.x, v.y), fmaxf(v.z, v.w));
#pragma unroll
        for (int o = 16; o > 0; o >>= 1) m = fmaxf(m, __shfl_xor_sync(0xffffffff, m, o));
        float sum = 0.0f;
        if (lane < 10)
            sum = __expf(v.x - m) + __expf(v.y - m) + __expf(v.z - m) + __expf(v.w - m);
#pragma unroll
        for (int o = 16; o > 0; o >>= 1) sum += __shfl_xor_sync(0xffffffff, sum, o);
        float l = m + logf(sum);
        if (lane < 10) {
            float4 o4 = make_float4(v.x - l, v.y - l, v.z - l, v.w - l);
            *(float4*)&out[n * OC + lane * 4] = o4;
        }
    }
}

// ---------------- launch: fork CSR build onto a side stream --------------------
extern "C" void kernel_launch(void* const* d_in, const int* in_sizes, int n_in,
                              void* d_out, int out_size) {
    const float* x      = (const float*)d_in[0];
    const void*  ei     = d_in[1];
    const float* W1     = (const float*)d_in[2];
    const float* a1_src = (const float*)d_in[3];
    const float* a1_dst = (const float*)d_in[4];
    const float* b1     = (const float*)d_in[5];
    const float* W2     = (const float*)d_in[6];
    const float* a2_src = (const float*)d_in[7];
    const float* a2_dst = (const float*)d_in[8];
    const float* b2     = (const float*)d_in[9];
    float* out = (float*)d_out;

    static cudaStream_t s2 = nullptr;
    static cudaEvent_t evFork = nullptr, evJoin = nullptr;
    if (s2 == nullptr) {
        cudaStreamCreateWithFlags(&s2, cudaStreamNonBlocking);
        cudaEventCreateWithFlags(&evFork, cudaEventDisableTiming);
        cudaEventCreateWithFlags(&evJoin, cudaEventDisableTiming);
    }

    cudaEventRecord(evFork, 0);
    cudaStreamWaitEvent(s2, evFork, 0);

    // Branch B (s2): CSR build front
    k_detect<<<1, 32, 0, s2>>>((const unsigned int*)ei);
    k_zero<<<(NN + 255) / 256, 256, 0, s2>>>();
    k_count<<<(EE / 4 + 255) / 256, 256, 0, s2>>>(ei);

    // Branch A (stream 0): tf32 GEMM1 (profiled control)
    k_gemm1<<<(NN + 127) / 128, 256>>>(x, W1, a1_src, a1_dst);

    // Branch B continued
    k_scan1<<<NBLK, SCAN_B, 0, s2>>>();
    k_scan3<<<(NN + 255) / 256, 256, 0, s2>>>();
    k_fill<<<(EE / 4 + 255) / 256, 256, 0, s2>>>(ei);
    cudaEventRecord(evJoin, s2);

    cudaStreamWaitEvent(0, evJoin, 0);
    k_node_agg1<<<AGG_BLOCKS, 256>>>(b1);
    k_gemm2<<<(NN + 255) / 256, 256>>>(W2, a2_src, a2_dst);
    k_node_agg2<<<AGG_BLOCKS, 256>>>(b2, out);
}

// round 15
// speedup vs baseline: 1.1459x; 1.1459x over previous
#include <cuda_runtime.h>
#include <math.h>
#include <stdint.h>

#define NN   50000
#define EE   800000
#define HH   8
#define H1C  128
#define OC   40
#define SLOPE 0.2f
#define NEG_INF __int_as_float(0xff800000)

#define SCAN_B 1024
#define NBLK   ((NN + SCAN_B - 1) / SCAN_B)   // 49
#define NSPLIT 25088                           // 98 tiles x 256 rows
#define NTILES_LO 98
#define NTILES_HI ((NN - NSPLIT + 255) / 256)  // 98

// ---------------- scratch -----------------------------------------------------
__device__ float g_h1[NN * H1C];
__device__ float g_as1[NN * HH];
__device__ float g_ad1[NN * HH];
__device__ float g_agg1[NN * H1C];
__device__ float g_h2[NN * OC];
__device__ float g_as2[NN];
__device__ float g_ad2[NN];
__device__ int   g_deg[NN];
__device__ int   g_off[NN];
__device__ int   g_cur[NN];
__device__ int   g_bsum[NBLK];
__device__ int   g_boff[NBLK];
__device__ int   g_list[EE];           // src ids grouped by dst
__device__ int   g_is64;

// ---------------- helpers -----------------------------------------------------
__device__ __forceinline__ float leaky(float v) {
    return (v >= 0.0f) ? v : SLOPE * v;
}
__device__ __forceinline__ uint32_t f2tf(float f) {
    uint32_t u;
    asm("cvt.rna.tf32.f32 %0, %1;" : "=r"(u) : "f"(f));
    return u;
}
__device__ __forceinline__ void mma_tf32(float* d, const uint32_t* a, const uint32_t* b) {
    asm volatile(
        "mma.sync.aligned.m16n8k8.row.col.f32.tf32.tf32.f32 "
        "{%0,%1,%2,%3}, {%4,%5,%6,%7}, {%8,%9}, {%0,%1,%2,%3};\n"
        : "+f"(d[0]), "+f"(d[1]), "+f"(d[2]), "+f"(d[3])
        : "r"(a[0]), "r"(a[1]), "r"(a[2]), "r"(a[3]), "r"(b[0]), "r"(b[1]));
}

// ---------------- CSR build (R13-proven) ---------------------------------------
__global__ void k_detect(const unsigned int* p) {
    int t = threadIdx.x;                   // 32
    unsigned int v = p[2 * t + 1];
    int any = __any_sync(0xffffffff, v != 0);
    if (t == 0) g_is64 = any ? 0 : 1;
}

__global__ void k_zero() {
    int i = blockIdx.x * blockDim.x + threadIdx.x;
    if (i < NN) g_deg[i] = 0;
}

__global__ void k_count(const void* __restrict__ ei) {
    int base = (blockIdx.x * blockDim.x + threadIdx.x) * 4;
    if (base >= EE) return;
    int d0, d1, d2, d3;
    if (g_is64) {
        const longlong2* p = (const longlong2*)((const long long*)ei + EE + base);
        longlong2 a = p[0];
        longlong2 b = p[1];
        d0 = (int)a.x; d1 = (int)a.y; d2 = (int)b.x; d3 = (int)b.y;
    } else {
        int4 a = *(const int4*)((const int*)ei + EE + base);
        d0 = a.x; d1 = a.y; d2 = a.z; d3 = a.w;
    }
    atomicAdd(&g_deg[d0], 1);
    atomicAdd(&g_deg[d1], 1);
    atomicAdd(&g_deg[d2], 1);
    atomicAdd(&g_deg[d3], 1);
}

__global__ void k_scan1() {
    __shared__ int warpsum[32];
    int tid = threadIdx.x;
    int i = blockIdx.x * SCAN_B + tid;
    int v = (i < NN) ? g_deg[i] : 0;
    int x = v;
#pragma unroll
    for (int o = 1; o < 32; o <<= 1) {
        int y = __shfl_up_sync(0xffffffff, x, o);
        if ((tid & 31) >= o) x += y;
    }
    if ((tid & 31) == 31) warpsum[tid >> 5] = x;
    __syncthreads();
    if (tid < 32) {
        int w = warpsum[tid];
#pragma unroll
        for (int o = 1; o < 32; o <<= 1) {
            int y = __shfl_up_sync(0xffffffff, w, o);
            if (tid >= o) w += y;
        }
        warpsum[tid] = w;
    }
    __syncthreads();
    int blockpart = (tid >= 32) ? warpsum[(tid >> 5) - 1] : 0;
    if (i < NN) g_off[i] = blockpart + x - v;
    if (tid == SCAN_B - 1) g_bsum[blockIdx.x] = blockpart + x;
}

__global__ void k_scan2() {
    int tid = threadIdx.x;                 // 64
    int v = (tid < NBLK) ? g_bsum[tid] : 0;
    int x = v;
#pragma unroll
    for (int o = 1; o < 32; o <<= 1) {
        int y = __shfl_up_sync(0xffffffff, x, o);
        if ((tid & 31) >= o) x += y;
    }
    __shared__ int w0;
    if (tid == 31) w0 = x;
    __syncthreads();
    int excl = x - v + ((tid >= 32) ? w0 : 0);
    if (tid < NBLK) g_boff[tid] = excl;
}

__global__ void k_scan3() {
    int i = blockIdx.x * blockDim.x + threadIdx.x;
    if (i >= NN) return;
    int o = g_off[i] + g_boff[i / SCAN_B];
    g_off[i] = o;
    g_cur[i] = o;
}

__global__ void k_fill(const void* __restrict__ ei) {
    int base = (blockIdx.x * blockDim.x + threadIdx.x) * 4;
    if (base >= EE) return;
    int s0, s1, s2v, s3, d0, d1, d2, d3;
    if (g_is64) {
        const longlong2* ps = (const longlong2*)((const long long*)ei + base);
        const longlong2* pd = (const longlong2*)((const long long*)ei + EE + base);
        longlong2 sa = ps[0], sb = ps[1];
        longlong2 da = pd[0], db = pd[1];
        s0 = (int)sa.x; s1 = (int)sa.y; s2v = (int)sb.x; s3 = (int)sb.y;
        d0 = (int)da.x; d1 = (int)da.y; d2 = (int)db.x; d3 = (int)db.y;
    } else {
        int4 sa = *(const int4*)((const int*)ei + base);
        int4 da = *(const int4*)((const int*)ei + EE + base);
        s0 = sa.x; s1 = sa.y; s2v = sa.z; s3 = sa.w;
        d0 = da.x; d1 = da.y; d2 = da.z; d3 = da.w;
    }
    g_list[atomicAdd(&g_cur[d0], 1)] = s0;
    g_list[atomicAdd(&g_cur[d1], 1)] = s1;
    g_list[atomicAdd(&g_cur[d2], 1)] = s2v;
    g_list[atomicAdd(&g_cur[d3], 1)] = s3;
}

// ---------------- GEMM1: tf32 tensor-core, fused attention halves --------------
__global__ void k_gemm1(const float* __restrict__ X, const float* __restrict__ W,
                        const float* __restrict__ aS, const float* __restrict__ aD) {
    __shared__ float As[128][36];
    __shared__ float Bs[32][136];
    const int tid  = threadIdx.x;    // 256
    const int wid  = tid >> 5, lane = tid & 31;
    const int g    = lane >> 2, tg = lane & 3;
    const int wm   = wid >> 2, wn = wid & 3;
    const int m0   = wm * 64, n0 = wn * 32;
    const int row0 = blockIdx.x * 128;

    float d[4][4][4];
#pragma unroll
    for (int mi = 0; mi < 4; mi++)
#pragma unroll
        for (int nj = 0; nj < 4; nj++)
#pragma unroll
            for (int r = 0; r < 4; r++) d[mi][nj][r] = 0.0f;

    for (int kc = 0; kc < 128; kc += 32) {
#pragma unroll
        for (int it = 0; it < 4; it++) {
            int f = tid + it * 256;
            int r = f >> 3, q = f & 7;
            int gr = row0 + r;
            float4 v = make_float4(0.f, 0.f, 0.f, 0.f);
            if (gr < NN) v = *(const float4*)&X[gr * 128 + kc + q * 4];
            uint4 t = make_uint4(f2tf(v.x), f2tf(v.y), f2tf(v.z), f2tf(v.w));
            *(uint4*)&As[r][q * 4] = t;
        }
#pragma unroll
        for (int it = 0; it < 4; it++) {
            int f = tid + it * 256;
            int r = f >> 5, q = f & 31;
            float4 v = *(const float4*)&W[(kc + r) * 128 + q * 4];
            uint4 t = make_uint4(f2tf(v.x), f2tf(v.y), f2tf(v.z), f2tf(v.w));
            *(uint4*)&Bs[r][q * 4] = t;
        }
        __syncthreads();
#pragma unroll
        for (int ks = 0; ks < 4; ks++) {
            uint32_t a[4][4];
#pragma unroll
            for (int mi = 0; mi < 4; mi++) {
                int ra = m0 + mi * 16 + g;
                a[mi][0] = __float_as_uint(As[ra][ks * 8 + tg]);
                a[mi][1] = __float_as_uint(As[ra + 8][ks * 8 + tg]);
                a[mi][2] = __float_as_uint(As[ra][ks * 8 + tg + 4]);
                a[mi][3] = __float_as_uint(As[ra + 8][ks * 8 + tg + 4]);
            }
            uint32_t b[4][2];
#pragma unroll
            for (int nj = 0; nj < 4; nj++) {
                int cb = n0 + nj * 8 + g;
                b[nj][0] = __float_as_uint(Bs[ks * 8 + tg][cb]);
                b[nj][1] = __float_as_uint(Bs[ks * 8 + tg + 4][cb]);
            }
#pragma unroll
            for (int mi = 0; mi < 4; mi++)
#pragma unroll
                for (int nj = 0; nj < 4; nj++)
                    mma_tf32(d[mi][nj], a[mi], b[nj]);
        }
        __syncthreads();
    }

    float a_s0[4], a_s1[4], a_d0[4], a_d1[4];
#pragma unroll
    for (int nj = 0; nj < 4; nj++) {
        int c = n0 + nj * 8 + tg * 2;
        a_s0[nj] = aS[c]; a_s1[nj] = aS[c + 1];
        a_d0[nj] = aD[c]; a_d1[nj] = aD[c + 1];
    }
    const int h0 = n0 >> 4;

#pragma unroll
    for (int mi = 0; mi < 4; mi++) {
        int rowA = row0 + m0 + mi * 16 + g;
        int rowB = rowA + 8;
        bool okA = rowA < NN, okB = rowB < NN;
#pragma unroll
        for (int nj = 0; nj < 4; nj++) {
            int col = n0 + nj * 8 + tg * 2;
            if (okA) *(float2*)&g_h1[rowA * 128 + col] = make_float2(d[mi][nj][0], d[mi][nj][1]);
            if (okB) *(float2*)&g_h1[rowB * 128 + col] = make_float2(d[mi][nj][2], d[mi][nj][3]);
        }
        float pA0 = 0, pA1 = 0, pB0 = 0, pB1 = 0;
        float qA0 = 0, qA1 = 0, qB0 = 0, qB1 = 0;
#pragma unroll
        for (int nj = 0; nj < 2; nj++) {
            pA0 += d[mi][nj][0] * a_s0[nj] + d[mi][nj][1] * a_s1[nj];
            pB0 += d[mi][nj][2] * a_s0[nj] + d[mi][nj][3] * a_s1[nj];
            qA0 += d[mi][nj][0] * a_d0[nj] + d[mi][nj][1] * a_d1[nj];
            qB0 += d[mi][nj][2] * a_d0[nj] + d[mi][nj][3] * a_d1[nj];
        }
#pragma unroll
        for (int nj = 2; nj < 4; nj++) {
            pA1 += d[mi][nj][0] * a_s0[nj] + d[mi][nj][1] * a_s1[nj];
            pB1 += d[mi][nj][2] * a_s0[nj] + d[mi][nj][3] * a_s1[nj];
            qA1 += d[mi][nj][0] * a_d0[nj] + d[mi][nj][1] * a_d1[nj];
            qB1 += d[mi][nj][2] * a_d0[nj] + d[mi][nj][3] * a_d1[nj];
        }
#pragma unroll
        for (int o = 1; o <= 2; o <<= 1) {
            pA0 += __shfl_xor_sync(0xffffffff, pA0, o);
            pA1 += __shfl_xor_sync(0xffffffff, pA1, o);
            pB0 += __shfl_xor_sync(0xffffffff, pB0, o);
            pB1 += __shfl_xor_sync(0xffffffff, pB1, o);
            qA0 += __shfl_xor_sync(0xffffffff, qA0, o);
            qA1 += __shfl_xor_sync(0xffffffff, qA1, o);
            qB0 += __shfl_xor_sync(0xffffffff, qB0, o);
            qB1 += __shfl_xor_sync(0xffffffff, qB1, o);
        }
        if (tg == 0) {
            if (okA) {
                g_as1[rowA * 8 + h0] = pA0; g_as1[rowA * 8 + h0 + 1] = pA1;
                g_ad1[rowA * 8 + h0] = qA0; g_ad1[rowA * 8 + h0 + 1] = qA1;
            }
            if (okB) {
                g_as1[rowB * 8 + h0] = pB0; g_as1[rowB * 8 + h0 + 1] = pB1;
                g_ad1[rowB * 8 + h0] = qB0; g_ad1[rowB * 8 + h0 + 1] = qB1;
            }
        }
    }
}

// ---------------- layer1 aggregation: static warp/node over [off, off+cnt) -----
__global__ void k_node_agg1(const float* __restrict__ b1, int off, int cnt) {
    int gtid = blockIdx.x * blockDim.x + threadIdx.x;
    int idx = gtid >> 5;
    if (idx >= cnt) return;
    int n = off + idx;
    int lane = gtid & 31;
    int my_h = lane >> 2;

    float ad = 0.0f, as_self = 0.0f;
    if (lane < 8) {
        ad      = g_ad1[n * 8 + lane];
        as_self = g_as1[n * 8 + lane];
    }
    float ex = (lane < 8) ? __expf(leaky(as_self + ad)) : 0.0f;
    float den = ex;
    float exb = __shfl_sync(0xffffffff, ex, my_h);
    float4 hv = *(const float4*)&g_h1[n * 128 + lane * 4];
    float4 acc = make_float4(exb * hv.x, exb * hv.y, exb * hv.z, exb * hv.w);

    int beg = g_off[n];
    int end = beg + g_deg[n];
    int i = beg;
    for (; i + 3 < end; i += 4) {
        int s0 = g_list[i], s1 = g_list[i + 1], s2 = g_list[i + 2], s3 = g_list[i + 3];
        float r0 = 0.f, r1 = 0.f, r2 = 0.f, r3 = 0.f;
        if (lane < 8) {
            r0 = g_as1[s0 * 8 + lane];
            r1 = g_as1[s1 * 8 + lane];
            r2 = g_as1[s2 * 8 + lane];
            r3 = g_as1[s3 * 8 + lane];
        }
        float4 h0 = *(const float4*)&g_h1[s0 * 128 + lane * 4];
        float4 h1 = *(const float4*)&g_h1[s1 * 128 + lane * 4];
        float4 h2 = *(const float4*)&g_h1[s2 * 128 + lane * 4];
        float4 h3 = *(const float4*)&g_h1[s3 * 128 + lane * 4];
        float e0 = (lane < 8) ? __expf(leaky(r0 + ad)) : 0.0f;
        float e1 = (lane < 8) ? __expf(leaky(r1 + ad)) : 0.0f;
        float e2 = (lane < 8) ? __expf(leaky(r2 + ad)) : 0.0f;
        float e3 = (lane < 8) ? __expf(leaky(r3 + ad)) : 0.0f;
        den += (e0 + e1) + (e2 + e3);
        float eb0 = __shfl_sync(0xffffffff, e0, my_h);
        float eb1 = __shfl_sync(0xffffffff, e1, my_h);
        float eb2 = __shfl_sync(0xffffffff, e2, my_h);
        float eb3 = __shfl_sync(0xffffffff, e3, my_h);
        acc.x += eb0 * h0.x + eb1 * h1.x + eb2 * h2.x + eb3 * h3.x;
        acc.y += eb0 * h0.y + eb1 * h1.y + eb2 * h2.y + eb3 * h3.y;
        acc.z += eb0 * h0.z + eb1 * h1.z + eb2 * h2.z + eb3 * h3.z;
        acc.w += eb0 * h0.w + eb1 * h1.w + eb2 * h2.w + eb3 * h3.w;
    }
    for (; i < end; i++) {
        int s = g_list[i];
        float e = 0.0f;
        if (lane < 8) e = __expf(leaky(g_as1[s * 8 + lane] + ad));
        den += e;
        float eb = __shfl_sync(0xffffffff, e, my_h);
        float4 h = *(const float4*)&g_h1[s * 128 + lane * 4];
        acc.x += eb * h.x; acc.y += eb * h.y;
        acc.z += eb * h.z; acc.w += eb * h.w;
    }
    float denb = __shfl_sync(0xffffffff, den, my_h);
    float inv = 1.0f / denb;
    float4 bv = *(const float4*)&b1[lane * 4];
    float4 o;
    o.x = fmaxf(acc.x * inv + bv.x, 0.0f);
    o.y = fmaxf(acc.y * inv + bv.y, 0.0f);
    o.z = fmaxf(acc.z * inv + bv.z, 0.0f);
    o.w = fmaxf(acc.w * inv + bv.w, 0.0f);
    *(float4*)&g_agg1[n * 128 + lane * 4] = o;
}

// ---------------- GEMM2: tf32, 256x40 tiles, tile-offset param -----------------
__global__ void k_gemm2(const float* __restrict__ W,
                        const float* __restrict__ aS, const float* __restrict__ aD,
                        int tile0) {
    __shared__ float As[256][36];
    __shared__ float Bs[32][40];
    const int tid  = threadIdx.x;   // 256
    const int wid  = tid >> 5, lane = tid & 31;
    const int g    = lane >> 2, tg = lane & 3;
    const int m0   = wid * 32;
    const int row0 = (blockIdx.x + tile0) * 256;

    float d[2][5][4];
#pragma unroll
    for (int mi = 0; mi < 2; mi++)
#pragma unroll
        for (int f = 0; f < 5; f++)
#pragma unroll
            for (int r = 0; r < 4; r++) d[mi][f][r] = 0.0f;

    for (int kc = 0; kc < 128; kc += 32) {
#pragma unroll
        for (int it = 0; it < 8; it++) {
            int f = tid + it * 256;
            int r = f >> 3, q = f & 7;
            int gr = row0 + r;
            float4 v = make_float4(0.f, 0.f, 0.f, 0.f);
            if (gr < NN) v = *(const float4*)&g_agg1[gr * 128 + kc + q * 4];
            uint4 t = make_uint4(f2tf(v.x), f2tf(v.y), f2tf(v.z), f2tf(v.w));
            *(uint4*)&As[r][q * 4] = t;
        }
        for (int f = tid; f < 320; f += 256) {
            int r = f / 10, q = f % 10;
            float4 v = *(const float4*)&W[(kc + r) * 40 + q * 4];
            uint4 t = make_uint4(f2tf(v.x), f2tf(v.y), f2tf(v.z), f2tf(v.w));
            *(uint4*)&Bs[r][q * 4] = t;
        }
        __syncthreads();
#pragma unroll
        for (int ks = 0; ks < 4; ks++) {
            uint32_t a[2][4];
#pragma unroll
            for (int mi = 0; mi < 2; mi++) {
                int ra = m0 + mi * 16 + g;
                a[mi][0] = __float_as_uint(As[ra][ks * 8 + tg]);
                a[mi][1] = __float_as_uint(As[ra + 8][ks * 8 + tg]);
                a[mi][2] = __float_as_uint(As[ra][ks * 8 + tg + 4]);
                a[mi][3] = __float_as_uint(As[ra + 8][ks * 8 + tg + 4]);
            }
            uint32_t b[5][2];
#pragma unroll
            for (int f = 0; f < 5; f++) {
                int cb = f * 8 + g;
                b[f][0] = __float_as_uint(Bs[ks * 8 + tg][cb]);
                b[f][1] = __float_as_uint(Bs[ks * 8 + tg + 4][cb]);
            }
#pragma unroll
            for (int mi = 0; mi < 2; mi++)
#pragma unroll
                for (int f = 0; f < 5; f++)
                    mma_tf32(d[mi][f], a[mi], b[f]);
        }
        __syncthreads();
    }

    float a_s0[5], a_s1[5], a_d0[5], a_d1[5];
#pragma unroll
    for (int f = 0; f < 5; f++) {
        int c = f * 8 + tg * 2;
        a_s0[f] = aS[c]; a_s1[f] = aS[c + 1];
        a_d0[f] = aD[c]; a_d1[f] = aD[c + 1];
    }

#pragma unroll
    for (int mi = 0; mi < 2; mi++) {
        int rowA = row0 + m0 + mi * 16 + g;
        int rowB = rowA + 8;
        bool okA = rowA < NN, okB = rowB < NN;
#pragma unroll
        for (int f = 0; f < 5; f++) {
            int col = f * 8 + tg * 2;
            if (okA) *(float2*)&g_h2[rowA * OC + col] = make_float2(d[mi][f][0], d[mi][f][1]);
            if (okB) *(float2*)&g_h2[rowB * OC + col] = make_float2(d[mi][f][2], d[mi][f][3]);
        }
        float pA = 0, pB = 0, qA = 0, qB = 0;
#pragma unroll
        for (int f = 0; f < 5; f++) {
            pA += d[mi][f][0] * a_s0[f] + d[mi][f][1] * a_s1[f];
            pB += d[mi][f][2] * a_s0[f] + d[mi][f][3] * a_s1[f];
            qA += d[mi][f][0] * a_d0[f] + d[mi][f][1] * a_d1[f];
            qB += d[mi][f][2] * a_d0[f] + d[mi][f][3] * a_d1[f];
        }
#pragma unroll
        for (int o = 1; o <= 2; o <<= 1) {
            pA += __shfl_xor_sync(0xffffffff, pA, o);
            pB += __shfl_xor_sync(0xffffffff, pB, o);
            qA += __shfl_xor_sync(0xffffffff, qA, o);
            qB += __shfl_xor_sync(0xffffffff, qB, o);
        }
        if (tg == 0) {
            if (okA) { g_as2[rowA] = pA; g_ad2[rowA] = qA; }
            if (okB) { g_as2[rowB] = pB; g_ad2[rowB] = qB; }
        }
    }
}

// ---------------- layer2 aggregation + log_softmax (R13-proven) ----------------
__global__ void k_node_agg2(const float* __restrict__ b2, float* __restrict__ out) {
    int gtid = blockIdx.x * blockDim.x + threadIdx.x;
    int n = gtid >> 5;
    if (n >= NN) return;
    int lane = gtid & 31;

    float ad = g_ad2[n];
    float ex = __expf(leaky(g_as2[n] + ad));
    float den = ex;
    float4 acc = make_float4(0.f, 0.f, 0.f, 0.f);
    if (lane < 10) {
        float4 h = *(const float4*)&g_h2[n * OC + lane * 4];
        acc.x = ex * h.x; acc.y = ex * h.y; acc.z = ex * h.z; acc.w = ex * h.w;
    }

    int beg = g_off[n];
    int end = beg + g_deg[n];
    int i = beg;
    for (; i + 1 < end; i += 2) {
        int s0 = g_list[i];
        int s1 = g_list[i + 1];
        float r0 = g_as2[s0];
        float r1 = g_as2[s1];
        float4 h0 = make_float4(0.f, 0.f, 0.f, 0.f);
        float4 h1 = make_float4(0.f, 0.f, 0.f, 0.f);
        if (lane < 10) {
            h0 = *(const float4*)&g_h2[s0 * OC + lane * 4];
            h1 = *(const float4*)&g_h2[s1 * OC + lane * 4];
        }
        float e0 = __expf(leaky(r0 + ad));
        float e1 = __expf(leaky(r1 + ad));
        den += e0 + e1;
        acc.x += e0 * h0.x + e1 * h1.x;
        acc.y += e0 * h0.y + e1 * h1.y;
        acc.z += e0 * h0.z + e1 * h1.z;
        acc.w += e0 * h0.w + e1 * h1.w;
    }
    if (i < end) {
        int s = g_list[i];
        float e = __expf(leaky(g_as2[s] + ad));
        den += e;
        if (lane < 10) {
            float4 h = *(const float4*)&g_h2[s * OC + lane * 4];
            acc.x += e * h.x; acc.y += e * h.y;
            acc.z += e * h.z; acc.w += e * h.w;
        }
    }

    float inv = 1.0f / den;
    float4 v = make_float4(NEG_INF, NEG_INF, NEG_INF, NEG_INF);
    if (lane < 10) {
        v.x = acc.x * inv + b2[lane * 4];
        v.y = acc.y * inv + b2[lane * 4 + 1];
        v.z = acc.z * inv + b2[lane * 4 + 2];
        v.w = acc.w * inv + b2[lane * 4 + 3];
    }
    float m = fmaxf(fmaxf(v.x, v.y), fmaxf(v.z, v.w));
#pragma unroll
    for (int o = 16; o > 0; o >>= 1) m = fmaxf(m, __shfl_xor_sync(0xffffffff, m, o));
    float sum = 0.0f;
    if (lane < 10)
        sum = __expf(v.x - m) + __expf(v.y - m) + __expf(v.z - m) + __expf(v.w - m);
#pragma unroll
    for (int o = 16; o > 0; o >>= 1) sum += __shfl_xor_sync(0xffffffff, sum, o);
    float l = m + logf(sum);
    if (lane < 10) {
        float4 o4 = make_float4(v.x - l, v.y - l, v.z - l, v.w - l);
        *(float4*)&out[n * OC + lane * 4] = o4;
    }
}

// ---------------- launch: fork CSR; pipeline agg1/gemm2 halves ----------------
extern "C" void kernel_launch(void* const* d_in, const int* in_sizes, int n_in,
                              void* d_out, int out_size) {
    const float* x      = (const float*)d_in[0];
    const void*  ei     = d_in[1];
    const float* W1     = (const float*)d_in[2];
    const float* a1_src = (const float*)d_in[3];
    const float* a1_dst = (const float*)d_in[4];
    const float* b1     = (const float*)d_in[5];
    const float* W2     = (const float*)d_in[6];
    const float* a2_src = (const float*)d_in[7];
    const float* a2_dst = (const float*)d_in[8];
    const float* b2     = (const float*)d_in[9];
    float* out = (float*)d_out;

    static cudaStream_t s2 = nullptr;
    static cudaEvent_t evFork = nullptr, evJoin = nullptr, evA = nullptr, evB = nullptr;
    if (s2 == nullptr) {
        cudaStreamCreateWithFlags(&s2, cudaStreamNonBlocking);
        cudaEventCreateWithFlags(&evFork, cudaEventDisableTiming);
        cudaEventCreateWithFlags(&evJoin, cudaEventDisableTiming);
        cudaEventCreateWithFlags(&evA, cudaEventDisableTiming);
        cudaEventCreateWithFlags(&evB, cudaEventDisableTiming);
    }

    cudaEventRecord(evFork, 0);
    cudaStreamWaitEvent(s2, evFork, 0);

    // Branch B (s2): CSR build front
    k_detect<<<1, 32, 0, s2>>>((const unsigned int*)ei);
    k_zero<<<(NN + 255) / 256, 256, 0, s2>>>();
    k_count<<<(EE / 4 + 255) / 256, 256, 0, s2>>>(ei);

    // Branch A (stream 0): tf32 GEMM1 (profiled control)
    k_gemm1<<<(NN + 127) / 128, 256>>>(x, W1, a1_src, a1_dst);

    // Branch B continued
    k_scan1<<<NBLK, SCAN_B, 0, s2>>>();
    k_scan2<<<1, 64, 0, s2>>>();
    k_scan3<<<(NN + 255) / 256, 256, 0, s2>>>();
    k_fill<<<(EE / 4 + 255) / 256, 256, 0, s2>>>(ei);
    cudaEventRecord(evJoin, s2);

    // s0: agg1 low half, then (overlapped) high half
    cudaStreamWaitEvent(0, evJoin, 0);
    k_node_agg1<<<(NSPLIT * 32 + 255) / 256, 256>>>(b1, 0, NSPLIT);
    cudaEventRecord(evA, 0);
    k_node_agg1<<<((NN - NSPLIT) * 32 + 255) / 256, 256>>>(b1, NSPLIT, NN - NSPLIT);

    // s2: gemm2 on low half, overlapping agg1 high half
    cudaStreamWaitEvent(s2, evA, 0);
    k_gemm2<<<NTILES_LO, 256, 0, s2>>>(W2, a2_src, a2_dst, 0);
    cudaEventRecord(evB, s2);

    // s0: gemm2 high half after agg1_hi, then join and final agg2
    k_gemm2<<<NTILES_HI, 256>>>(W2, a2_src, a2_dst, NTILES_LO);
    cudaStreamWaitEvent(0, evB, 0);
    k_node_agg2<<<(NN * 32 + 255) / 256, 256>>>(b2, out);
}

// round 17
// speedup vs baseline: 1.1821x; 1.0316x over previous
#include <cuda_runtime.h>
#include <math.h>
#include <stdint.h>

#define NN   50000
#define EE   800000
#define HH   8
#define H1C  128
#define OC   40
#define SLOPE 0.2f
#define NEG_INF __int_as_float(0xff800000)

#define SCAN_B 1024
#define NBLK   ((NN + SCAN_B - 1) / SCAN_B)   // 49

// ---------------- scratch -----------------------------------------------------
__device__ float g_h1[NN * H1C];
__device__ float g_as1[NN * HH];
__device__ float g_ad1[NN * HH];
__device__ float g_agg1[NN * H1C];
__device__ float g_h2[NN * OC];
__device__ float g_as2[NN];
__device__ float g_ad2[NN];
__device__ int   g_deg[NN];
__device__ int   g_off[NN];
__device__ int   g_cur[NN];
__device__ int   g_bsum[NBLK];
__device__ int   g_boff[NBLK];
__device__ int   g_list[EE];           // src ids grouped by dst
__device__ int   g_is64;

// ---------------- helpers -----------------------------------------------------
__device__ __forceinline__ float leaky(float v) {
    return (v >= 0.0f) ? v : SLOPE * v;
}
// raw fp32 bits fed to tf32 mma: HW reads bits[31:13] (truncation) — valid tf32.
__device__ __forceinline__ void mma_tf32(float* d, const uint32_t* a, const uint32_t* b) {
    asm volatile(
        "mma.sync.aligned.m16n8k8.row.col.f32.tf32.tf32.f32 "
        "{%0,%1,%2,%3}, {%4,%5,%6,%7}, {%8,%9}, {%0,%1,%2,%3};\n"
        : "+f"(d[0]), "+f"(d[1]), "+f"(d[2]), "+f"(d[3])
        : "r"(a[0]), "r"(a[1]), "r"(a[2]), "r"(a[3]), "r"(b[0]), "r"(b[1]));
}

// ---------------- CSR build ----------------------------------------------------
// fused: zero deg + dtype probe (block 0, warp 0)
__global__ void k_zero_detect(const unsigned int* p) {
    int i = blockIdx.x * blockDim.x + threadIdx.x;
    if (i < NN) g_deg[i] = 0;
    if (blockIdx.x == 0 && threadIdx.x < 32) {
        unsigned int v = p[2 * threadIdx.x + 1];
        int any = __any_sync(0xffffffff, v != 0);
        if (threadIdx.x == 0) g_is64 = any ? 0 : 1;
    }
}

__global__ void k_count(const void* __restrict__ ei) {
    int base = (blockIdx.x * blockDim.x + threadIdx.x) * 4;
    if (base >= EE) return;
    int d0, d1, d2, d3;
    if (g_is64) {
        const longlong2* p = (const longlong2*)((const long long*)ei + EE + base);
        longlong2 a = p[0];
        longlong2 b = p[1];
        d0 = (int)a.x; d1 = (int)a.y; d2 = (int)b.x; d3 = (int)b.y;
    } else {
        int4 a = *(const int4*)((const int*)ei + EE + base);
        d0 = a.x; d1 = a.y; d2 = a.z; d3 = a.w;
    }
    atomicAdd(&g_deg[d0], 1);
    atomicAdd(&g_deg[d1], 1);
    atomicAdd(&g_deg[d2], 1);
    atomicAdd(&g_deg[d3], 1);
}

__global__ void k_scan1() {
    __shared__ int warpsum[32];
    int tid = threadIdx.x;
    int i = blockIdx.x * SCAN_B + tid;
    int v = (i < NN) ? g_deg[i] : 0;
    int x = v;
#pragma unroll
    for (int o = 1; o < 32; o <<= 1) {
        int y = __shfl_up_sync(0xffffffff, x, o);
        if ((tid & 31) >= o) x += y;
    }
    if ((tid & 31) == 31) warpsum[tid >> 5] = x;
    __syncthreads();
    if (tid < 32) {
        int w = warpsum[tid];
#pragma unroll
        for (int o = 1; o < 32; o <<= 1) {
            int y = __shfl_up_sync(0xffffffff, w, o);
            if (tid >= o) w += y;
        }
        warpsum[tid] = w;
    }
    __syncthreads();
    int blockpart = (tid >= 32) ? warpsum[(tid >> 5) - 1] : 0;
    if (i < NN) g_off[i] = blockpart + x - v;
    if (tid == SCAN_B - 1) g_bsum[blockIdx.x] = blockpart + x;
}

__global__ void k_scan2() {
    int tid = threadIdx.x;                 // 64
    int v = (tid < NBLK) ? g_bsum[tid] : 0;
    int x = v;
#pragma unroll
    for (int o = 1; o < 32; o <<= 1) {
        int y = __shfl_up_sync(0xffffffff, x, o);
        if ((tid & 31) >= o) x += y;
    }
    __shared__ int w0;
    if (tid == 31) w0 = x;
    __syncthreads();
    int excl = x - v + ((tid >= 32) ? w0 : 0);
    if (tid < NBLK) g_boff[tid] = excl;
}

__global__ void k_scan3() {
    int i = blockIdx.x * blockDim.x + threadIdx.x;
    if (i >= NN) return;
    int o = g_off[i] + g_boff[i / SCAN_B];
    g_off[i] = o;
    g_cur[i] = o;
}

__global__ void k_fill(const void* __restrict__ ei) {
    int base = (blockIdx.x * blockDim.x + threadIdx.x) * 4;
    if (base >= EE) return;
    int s0, s1, s2v, s3, d0, d1, d2, d3;
    if (g_is64) {
        const longlong2* ps = (const longlong2*)((const long long*)ei + base);
        const longlong2* pd = (const longlong2*)((const long long*)ei + EE + base);
        longlong2 sa = ps[0], sb = ps[1];
        longlong2 da = pd[0], db = pd[1];
        s0 = (int)sa.x; s1 = (int)sa.y; s2v = (int)sb.x; s3 = (int)sb.y;
        d0 = (int)da.x; d1 = (int)da.y; d2 = (int)db.x; d3 = (int)db.y;
    } else {
        int4 sa = *(const int4*)((const int*)ei + base);
        int4 da = *(const int4*)((const int*)ei + EE + base);
        s0 = sa.x; s1 = sa.y; s2v = sa.z; s3 = sa.w;
        d0 = da.x; d1 = da.y; d2 = da.z; d3 = da.w;
    }
    g_list[atomicAdd(&g_cur[d0], 1)] = s0;
    g_list[atomicAdd(&g_cur[d1], 1)] = s1;
    g_list[atomicAdd(&g_cur[d2], 1)] = s2v;
    g_list[atomicAdd(&g_cur[d3], 1)] = s3;
}

// ---------------- GEMM1: tf32 tensor-core, no-cvt loads, fused attn halves -----
__global__ void k_gemm1(const float* __restrict__ X, const float* __restrict__ W,
                        const float* __restrict__ aS, const float* __restrict__ aD) {
    __shared__ float As[128][36];
    __shared__ float Bs[32][136];
    const int tid  = threadIdx.x;    // 256
    const int wid  = tid >> 5, lane = tid & 31;
    const int g    = lane >> 2, tg = lane & 3;
    const int wm   = wid >> 2, wn = wid & 3;
    const int m0   = wm * 64, n0 = wn * 32;
    const int row0 = blockIdx.x * 128;

    float d[4][4][4];
#pragma unroll
    for (int mi = 0; mi < 4; mi++)
#pragma unroll
        for (int nj = 0; nj < 4; nj++)
#pragma unroll
            for (int r = 0; r < 4; r++) d[mi][nj][r] = 0.0f;

    for (int kc = 0; kc < 128; kc += 32) {
#pragma unroll
        for (int it = 0; it < 4; it++) {
            int f = tid + it * 256;
            int r = f >> 3, q = f & 7;
            int gr = row0 + r;
            float4 v = make_float4(0.f, 0.f, 0.f, 0.f);
            if (gr < NN) v = *(const float4*)&X[gr * 128 + kc + q * 4];
            *(float4*)&As[r][q * 4] = v;
        }
#pragma unroll
        for (int it = 0; it < 4; it++) {
            int f = tid + it * 256;
            int r = f >> 5, q = f & 31;
            *(float4*)&Bs[r][q * 4] = *(const float4*)&W[(kc + r) * 128 + q * 4];
        }
        __syncthreads();
#pragma unroll
        for (int ks = 0; ks < 4; ks++) {
            uint32_t a[4][4];
#pragma unroll
            for (int mi = 0; mi < 4; mi++) {
                int ra = m0 + mi * 16 + g;
                a[mi][0] = __float_as_uint(As[ra][ks * 8 + tg]);
                a[mi][1] = __float_as_uint(As[ra + 8][ks * 8 + tg]);
                a[mi][2] = __float_as_uint(As[ra][ks * 8 + tg + 4]);
                a[mi][3] = __float_as_uint(As[ra + 8][ks * 8 + tg + 4]);
            }
            uint32_t b[4][2];
#pragma unroll
            for (int nj = 0; nj < 4; nj++) {
                int cb = n0 + nj * 8 + g;
                b[nj][0] = __float_as_uint(Bs[ks * 8 + tg][cb]);
                b[nj][1] = __float_as_uint(Bs[ks * 8 + tg + 4][cb]);
            }
#pragma unroll
            for (int mi = 0; mi < 4; mi++)
#pragma unroll
                for (int nj = 0; nj < 4; nj++)
                    mma_tf32(d[mi][nj], a[mi], b[nj]);
        }
        __syncthreads();
    }

    float a_s0[4], a_s1[4], a_d0[4], a_d1[4];
#pragma unroll
    for (int nj = 0; nj < 4; nj++) {
        int c = n0 + nj * 8 + tg * 2;
        a_s0[nj] = aS[c]; a_s1[nj] = aS[c + 1];
        a_d0[nj] = aD[c]; a_d1[nj] = aD[c + 1];
    }
    const int h0 = n0 >> 4;

#pragma unroll
    for (int mi = 0; mi < 4; mi++) {
        int rowA = row0 + m0 + mi * 16 + g;
        int rowB = rowA + 8;
        bool okA = rowA < NN, okB = rowB < NN;
#pragma unroll
        for (int nj = 0; nj < 4; nj++) {
            int col = n0 + nj * 8 + tg * 2;
            if (okA) *(float2*)&g_h1[rowA * 128 + col] = make_float2(d[mi][nj][0], d[mi][nj][1]);
            if (okB) *(float2*)&g_h1[rowB * 128 + col] = make_float2(d[mi][nj][2], d[mi][nj][3]);
        }
        float pA0 = 0, pA1 = 0, pB0 = 0, pB1 = 0;
        float qA0 = 0, qA1 = 0, qB0 = 0, qB1 = 0;
#pragma unroll
        for (int nj = 0; nj < 2; nj++) {
            pA0 += d[mi][nj][0] * a_s0[nj] + d[mi][nj][1] * a_s1[nj];
            pB0 += d[mi][nj][2] * a_s0[nj] + d[mi][nj][3] * a_s1[nj];
            qA0 += d[mi][nj][0] * a_d0[nj] + d[mi][nj][1] * a_d1[nj];
            qB0 += d[mi][nj][2] * a_d0[nj] + d[mi][nj][3] * a_d1[nj];
        }
#pragma unroll
        for (int nj = 2; nj < 4; nj++) {
            pA1 += d[mi][nj][0] * a_s0[nj] + d[mi][nj][1] * a_s1[nj];
            pB1 += d[mi][nj][2] * a_s0[nj] + d[mi][nj][3] * a_s1[nj];
            qA1 += d[mi][nj][0] * a_d0[nj] + d[mi][nj][1] * a_d1[nj];
            qB1 += d[mi][nj][2] * a_d0[nj] + d[mi][nj][3] * a_d1[nj];
        }
#pragma unroll
        for (int o = 1; o <= 2; o <<= 1) {
            pA0 += __shfl_xor_sync(0xffffffff, pA0, o);
            pA1 += __shfl_xor_sync(0xffffffff, pA1, o);
            pB0 += __shfl_xor_sync(0xffffffff, pB0, o);
            pB1 += __shfl_xor_sync(0xffffffff, pB1, o);
            qA0 += __shfl_xor_sync(0xffffffff, qA0, o);
            qA1 += __shfl_xor_sync(0xffffffff, qA1, o);
            qB0 += __shfl_xor_sync(0xffffffff, qB0, o);
            qB1 += __shfl_xor_sync(0xffffffff, qB1, o);
        }
        if (tg == 0) {
            if (okA) {
                g_as1[rowA * 8 + h0] = pA0; g_as1[rowA * 8 + h0 + 1] = pA1;
                g_ad1[rowA * 8 + h0] = qA0; g_ad1[rowA * 8 + h0 + 1] = qA1;
            }
            if (okB) {
                g_as1[rowB * 8 + h0] = pB0; g_as1[rowB * 8 + h0 + 1] = pB1;
                g_ad1[rowB * 8 + h0] = qB0; g_ad1[rowB * 8 + h0 + 1] = qB1;
            }
        }
    }
}

// ---------------- layer1 aggregation: warp/node, 4-deep pipeline (R13) ---------
__global__ void k_node_agg1(const float* __restrict__ b1) {
    int gtid = blockIdx.x * blockDim.x + threadIdx.x;
    int n = gtid >> 5;
    if (n >= NN) return;
    int lane = gtid & 31;
    int my_h = lane >> 2;

    float ad = 0.0f, as_self = 0.0f;
    if (lane < 8) {
        ad      = g_ad1[n * 8 + lane];
        as_self = g_as1[n * 8 + lane];
    }
    float ex = (lane < 8) ? __expf(leaky(as_self + ad)) : 0.0f;
    float den = ex;
    float exb = __shfl_sync(0xffffffff, ex, my_h);
    float4 hv = *(const float4*)&g_h1[n * 128 + lane * 4];
    float4 acc = make_float4(exb * hv.x, exb * hv.y, exb * hv.z, exb * hv.w);

    int beg = g_off[n];
    int end = beg + g_deg[n];
    int i = beg;
    for (; i + 3 < end; i += 4) {
        int s0 = g_list[i], s1 = g_list[i + 1], s2 = g_list[i + 2], s3 = g_list[i + 3];
        float r0 = 0.f, r1 = 0.f, r2 = 0.f, r3 = 0.f;
        if (lane < 8) {
            r0 = g_as1[s0 * 8 + lane];
            r1 = g_as1[s1 * 8 + lane];
            r2 = g_as1[s2 * 8 + lane];
            r3 = g_as1[s3 * 8 + lane];
        }
        float4 h0 = *(const float4*)&g_h1[s0 * 128 + lane * 4];
        float4 h1 = *(const float4*)&g_h1[s1 * 128 + lane * 4];
        float4 h2 = *(const float4*)&g_h1[s2 * 128 + lane * 4];
        float4 h3 = *(const float4*)&g_h1[s3 * 128 + lane * 4];
        float e0 = (lane < 8) ? __expf(leaky(r0 + ad)) : 0.0f;
        float e1 = (lane < 8) ? __expf(leaky(r1 + ad)) : 0.0f;
        float e2 = (lane < 8) ? __expf(leaky(r2 + ad)) : 0.0f;
        float e3 = (lane < 8) ? __expf(leaky(r3 + ad)) : 0.0f;
        den += (e0 + e1) + (e2 + e3);
        float eb0 = __shfl_sync(0xffffffff, e0, my_h);
        float eb1 = __shfl_sync(0xffffffff, e1, my_h);
        float eb2 = __shfl_sync(0xffffffff, e2, my_h);
        float eb3 = __shfl_sync(0xffffffff, e3, my_h);
        acc.x += eb0 * h0.x + eb1 * h1.x + eb2 * h2.x + eb3 * h3.x;
        acc.y += eb0 * h0.y + eb1 * h1.y + eb2 * h2.y + eb3 * h3.y;
        acc.z += eb0 * h0.z + eb1 * h1.z + eb2 * h2.z + eb3 * h3.z;
        acc.w += eb0 * h0.w + eb1 * h1.w + eb2 * h2.w + eb3 * h3.w;
    }
    for (; i < end; i++) {
        int s = g_list[i];
        float e = 0.0f;
        if (lane < 8) e = __expf(leaky(g_as1[s * 8 + lane] + ad));
        den += e;
        float eb = __shfl_sync(0xffffffff, e, my_h);
        float4 h = *(const float4*)&g_h1[s * 128 + lane * 4];
        acc.x += eb * h.x; acc.y += eb * h.y;
        acc.z += eb * h.z; acc.w += eb * h.w;
    }
    float denb = __shfl_sync(0xffffffff, den, my_h);
    float inv = 1.0f / denb;
    float4 bv = *(const float4*)&b1[lane * 4];
    float4 o;
    o.x = fmaxf(acc.x * inv + bv.x, 0.0f);
    o.y = fmaxf(acc.y * inv + bv.y, 0.0f);
    o.z = fmaxf(acc.z * inv + bv.z, 0.0f);
    o.w = fmaxf(acc.w * inv + bv.w, 0.0f);
    *(float4*)&g_agg1[n * 128 + lane * 4] = o;
}

// ---------------- GEMM2: tf32 tensor-core, no-cvt loads ------------------------
__global__ void k_gemm2(const float* __restrict__ W,
                        const float* __restrict__ aS, const float* __restrict__ aD) {
    __shared__ float As[256][36];
    __shared__ float Bs[32][40];
    const int tid  = threadIdx.x;   // 256
    const int wid  = tid >> 5, lane = tid & 31;
    const int g    = lane >> 2, tg = lane & 3;
    const int m0   = wid * 32;
    const int row0 = blockIdx.x * 256;

    float d[2][5][4];
#pragma unroll
    for (int mi = 0; mi < 2; mi++)
#pragma unroll
        for (int f = 0; f < 5; f++)
#pragma unroll
            for (int r = 0; r < 4; r++) d[mi][f][r] = 0.0f;

    for (int kc = 0; kc < 128; kc += 32) {
#pragma unroll
        for (int it = 0; it < 8; it++) {
            int f = tid + it * 256;
            int r = f >> 3, q = f & 7;
            int gr = row0 + r;
            float4 v = make_float4(0.f, 0.f, 0.f, 0.f);
            if (gr < NN) v = *(const float4*)&g_agg1[gr * 128 + kc + q * 4];
            *(float4*)&As[r][q * 4] = v;
        }
        for (int f = tid; f < 320; f += 256) {
            int r = f / 10, q = f % 10;
            *(float4*)&Bs[r][q * 4] = *(const float4*)&W[(kc + r) * 40 + q * 4];
        }
        __syncthreads();
#pragma unroll
        for (int ks = 0; ks < 4; ks++) {
            uint32_t a[2][4];
#pragma unroll
            for (int mi = 0; mi < 2; mi++) {
                int ra = m0 + mi * 16 + g;
                a[mi][0] = __float_as_uint(As[ra][ks * 8 + tg]);
                a[mi][1] = __float_as_uint(As[ra + 8][ks * 8 + tg]);
                a[mi][2] = __float_as_uint(As[ra][ks * 8 + tg + 4]);
                a[mi][3] = __float_as_uint(As[ra + 8][ks * 8 + tg + 4]);
            }
            uint32_t b[5][2];
#pragma unroll
            for (int f = 0; f < 5; f++) {
                int cb = f * 8 + g;
                b[f][0] = __float_as_uint(Bs[ks * 8 + tg][cb]);
                b[f][1] = __float_as_uint(Bs[ks * 8 + tg + 4][cb]);
            }
#pragma unroll
            for (int mi = 0; mi < 2; mi++)
#pragma unroll
                for (int f = 0; f < 5; f++)
                    mma_tf32(d[mi][f], a[mi], b[f]);
        }
        __syncthreads();
    }

    float a_s0[5], a_s1[5], a_d0[5], a_d1[5];
#pragma unroll
    for (int f = 0; f < 5; f++) {
        int c = f * 8 + tg * 2;
        a_s0[f] = aS[c]; a_s1[f] = aS[c + 1];
        a_d0[f] = aD[c]; a_d1[f] = aD[c + 1];
    }

#pragma unroll
    for (int mi = 0; mi < 2; mi++) {
        int rowA = row0 + m0 + mi * 16 + g;
        int rowB = rowA + 8;
        bool okA = rowA < NN, okB = rowB < NN;
#pragma unroll
        for (int f = 0; f < 5; f++) {
            int col = f * 8 + tg * 2;
            if (okA) *(float2*)&g_h2[rowA * OC + col] = make_float2(d[mi][f][0], d[mi][f][1]);
            if (okB) *(float2*)&g_h2[rowB * OC + col] = make_float2(d[mi][f][2], d[mi][f][3]);
        }
        float pA = 0, pB = 0, qA = 0, qB = 0;
#pragma unroll
        for (int f = 0; f < 5; f++) {
            pA += d[mi][f][0] * a_s0[f] + d[mi][f][1] * a_s1[f];
            pB += d[mi][f][2] * a_s0[f] + d[mi][f][3] * a_s1[f];
            qA += d[mi][f][0] * a_d0[f] + d[mi][f][1] * a_d1[f];
            qB += d[mi][f][2] * a_d0[f] + d[mi][f][3] * a_d1[f];
        }
#pragma unroll
        for (int o = 1; o <= 2; o <<= 1) {
            pA += __shfl_xor_sync(0xffffffff, pA, o);
            pB += __shfl_xor_sync(0xffffffff, pB, o);
            qA += __shfl_xor_sync(0xffffffff, qA, o);
            qB += __shfl_xor_sync(0xffffffff, qB, o);
        }
        if (tg == 0) {
            if (okA) { g_as2[rowA] = pA; g_ad2[rowA] = qA; }
            if (okB) { g_as2[rowB] = pB; g_ad2[rowB] = qB; }
        }
    }
}

// ---------------- layer2 aggregation + log_softmax (R13) -----------------------
__global__ void k_node_agg2(const float* __restrict__ b2, float* __restrict__ out) {
    int gtid = blockIdx.x * blockDim.x + threadIdx.x;
    int n = gtid >> 5;
    if (n >= NN) return;
    int lane = gtid & 31;

    float ad = g_ad2[n];
    float ex = __expf(leaky(g_as2[n] + ad));
    float den = ex;
    float4 acc = make_float4(0.f, 0.f, 0.f, 0.f);
    if (lane < 10) {
        float4 h = *(const float4*)&g_h2[n * OC + lane * 4];
        acc.x = ex * h.x; acc.y = ex * h.y; acc.z = ex * h.z; acc.w = ex * h.w;
    }

    int beg = g_off[n];
    int end = beg + g_deg[n];
    int i = beg;
    for (; i + 1 < end; i += 2) {
        int s0 = g_list[i];
        int s1 = g_list[i + 1];
        float r0 = g_as2[s0];
        float r1 = g_as2[s1];
        float4 h0 = make_float4(0.f, 0.f, 0.f, 0.f);
        float4 h1 = make_float4(0.f, 0.f, 0.f, 0.f);
        if (lane < 10) {
            h0 = *(const float4*)&g_h2[s0 * OC + lane * 4];
            h1 = *(const float4*)&g_h2[s1 * OC + lane * 4];
        }
        float e0 = __expf(leaky(r0 + ad));
        float e1 = __expf(leaky(r1 + ad));
        den += e0 + e1;
        acc.x += e0 * h0.x + e1 * h1.x;
        acc.y += e0 * h0.y + e1 * h1.y;
        acc.z += e0 * h0.z + e1 * h1.z;
        acc.w += e0 * h0.w + e1 * h1.w;
    }
    if (i < end) {
        int s = g_list[i];
        float e = __expf(leaky(g_as2[s] + ad));
        den += e;
        if (lane < 10) {
            float4 h = *(const float4*)&g_h2[s * OC + lane * 4];
            acc.x += e * h.x; acc.y += e * h.y;
            acc.z += e * h.z; acc.w += e * h.w;
        }
    }

    float inv = 1.0f / den;
    float4 v = make_float4(NEG_INF, NEG_INF, NEG_INF, NEG_INF);
    if (lane < 10) {
        v.x = acc.x * inv + b2[lane * 4];
        v.y = acc.y * inv + b2[lane * 4 + 1];
        v.z = acc.z * inv + b2[lane * 4 + 2];
        v.w = acc.w * inv + b2[lane * 4 + 3];
    }
    float m = fmaxf(fmaxf(v.x, v.y), fmaxf(v.z, v.w));
#pragma unroll
    for (int o = 16; o > 0; o >>= 1) m = fmaxf(m, __shfl_xor_sync(0xffffffff, m, o));
    float sum = 0.0f;
    if (lane < 10)
        sum = __expf(v.x - m) + __expf(v.y - m) + __expf(v.z - m) + __expf(v.w - m);
#pragma unroll
    for (int o = 16; o > 0; o >>= 1) sum += __shfl_xor_sync(0xffffffff, sum, o);
    float l = m + logf(sum);
    if (lane < 10) {
        float4 o4 = make_float4(v.x - l, v.y - l, v.z - l, v.w - l);
        *(float4*)&out[n * OC + lane * 4] = o4;
    }
}

// ---------------- launch: fork CSR build onto a side stream (R13) --------------
extern "C" void kernel_launch(void* const* d_in, const int* in_sizes, int n_in,
                              void* d_out, int out_size) {
    const float* x      = (const float*)d_in[0];
    const void*  ei     = d_in[1];
    const float* W1     = (const float*)d_in[2];
    const float* a1_src = (const float*)d_in[3];
    const float* a1_dst = (const float*)d_in[4];
    const float* b1     = (const float*)d_in[5];
    const float* W2     = (const float*)d_in[6];
    const float* a2_src = (const float*)d_in[7];
    const float* a2_dst = (const float*)d_in[8];
    const float* b2     = (const float*)d_in[9];
    float* out = (float*)d_out;

    static cudaStream_t s2 = nullptr;
    static cudaEvent_t evFork = nullptr, evJoin = nullptr;
    if (s2 == nullptr) {
        cudaStreamCreateWithFlags(&s2, cudaStreamNonBlocking);
        cudaEventCreateWithFlags(&evFork, cudaEventDisableTiming);
        cudaEventCreateWithFlags(&evJoin, cudaEventDisableTiming);
    }

    cudaEventRecord(evFork, 0);
    cudaStreamWaitEvent(s2, evFork, 0);

    // Branch B (s2): CSR build front
    k_zero_detect<<<(NN + 255) / 256, 256, 0, s2>>>((const unsigned int*)ei);
    k_count<<<(EE / 4 + 255) / 256, 256, 0, s2>>>(ei);

    // Branch A (stream 0): tf32 GEMM1
    k_gemm1<<<(NN + 127) / 128, 256>>>(x, W1, a1_src, a1_dst);

    // Branch B continued
    k_scan1<<<NBLK, SCAN_B, 0, s2>>>();
    k_scan2<<<1, 64, 0, s2>>>();
    k_scan3<<<(NN + 255) / 256, 256, 0, s2>>>();
    k_fill<<<(EE / 4 + 255) / 256, 256, 0, s2>>>(ei);
    cudaEventRecord(evJoin, s2);

    cudaStreamWaitEvent(0, evJoin, 0);
    k_node_agg1<<<(NN * 32 + 255) / 256, 256>>>(b1);
    k_gemm2<<<(NN + 255) / 256, 256>>>(W2, a2_src, a2_dst);
    k_node_agg2<<<(NN * 32 + 255) / 256, 256>>>(b2, out);
}